// round 5
// baseline (speedup 1.0000x reference)
#include <cuda_runtime.h>

#define IMG_H 512
#define IMG_W 512
#define HW (IMG_H * IMG_W)

// Channel-last staging of the bilateral grids:
//   g1t: [b][z][y][x][32]  (2 MB)   g2t: [b][z][y][x][28] (27 real + 1 zero pad)
__device__ float g1t[8 * 8 * 16 * 16 * 32];
__device__ float g2t[8 * 8 * 16 * 16 * 28];

__global__ __launch_bounds__(256) void transpose_grids(
    const float* __restrict__ g1, const float* __restrict__ g2)
{
    const int i = blockIdx.x * 256 + threadIdx.x;
    // grid1: [b][32][8][16][16] -> [b][z][y][x][32]
    if (i < 8 * 32 * 8 * 256) {
        const int x = i & 15, y = (i >> 4) & 15, z = (i >> 8) & 7;
        const int c = (i >> 11) & 31, b = i >> 16;
        g1t[(((b * 8 + z) * 16 + y) * 16 + x) * 32 + c] = g1[i];
    }
    // grid2: [b][27][8][16][16] -> [b][z][y][x][28]
    if (i < 8 * 27 * 8 * 256) {
        const int x = i & 15, y = (i >> 4) & 15, z = (i >> 8) & 7;
        const int t = i >> 11;
        const int c = t % 27, b = t / 27;
        g2t[(((b * 8 + z) * 16 + y) * 16 + x) * 28 + c] = g2[i];
    }
    // zero the pad channel (c = 27)
    if (i < 8 * 8 * 256) {
        g2t[i * 28 + 27] = 0.0f;
    }
}

__global__ __launch_bounds__(256, 4) void bgrid_fused_kernel(
    const float* __restrict__ src,    // (8,3,512,512)
    const float* __restrict__ w1, const float* __restrict__ b1,
    const float* __restrict__ w2, const float* __restrict__ b2,
    const float* __restrict__ w3, const float* __restrict__ b3,
    const float* __restrict__ w4, const float* __restrict__ b4,
    float* __restrict__ out)          // (8,3,512,512)
{
    __shared__ float sw1[48];
    __shared__ float sb1[16];
    __shared__ float sw2[16];
    __shared__ float sw3[128];
    __shared__ float sb3[16];
    __shared__ float sw4[16];
    __shared__ float sb2s, sb4s;

    const int tid = threadIdx.x;
    if (tid < 48)  sw1[tid] = w1[tid];
    if (tid < 16) {
        sb1[tid] = b1[tid];
        sw2[tid] = w2[tid];
        sb3[tid] = b3[tid];
        sw4[tid] = w4[tid];
    }
    if (tid < 128) sw3[tid] = w3[tid];
    if (tid == 0) { sb2s = b2[0]; sb4s = b4[0]; }
    __syncthreads();

    const int idx = blockIdx.x * 256 + tid;
    const int px = idx & 511;
    const int py = (idx >> 9) & 511;
    const int pb = idx >> 18;

    // ---- src pixel ----
    const float* srcp = src + (pb * 3) * HW + py * IMG_W + px;
    const float s0 = srcp[0];
    const float s1 = srcp[HW];
    const float s2 = srcp[2 * HW];

    // ---- guide NN #1 ----
    float g = sb2s;
#pragma unroll
    for (int o = 0; o < 16; o++) {
        float t = sb1[o];
        t = fmaf(sw1[o * 3 + 0], s0, t);
        t = fmaf(sw1[o * 3 + 1], s1, t);
        t = fmaf(sw1[o * 3 + 2], s2, t);
        t = fmaxf(t, 0.0f);
        g = fmaf(sw2[o], t, g);
    }
    g = tanhf(g);

    // ---- xy lattice (Gh=Gw=16): fx in [0,14.97] so x1=x0+1 always valid ----
    const float fx = (float)px * (15.0f / 512.0f);
    const float fy = (float)py * (15.0f / 512.0f);
    const int x0 = (int)fx;
    const int y0 = (int)fy;
    const float wx = fx - (float)x0;
    const float wy = fy - (float)y0;
    const float wya[2] = {1.0f - wy, wy};
    const float wxa[2] = {1.0f - wx, wx};
    const int oxy[2][2] = {{y0 * 16 + x0,      y0 * 16 + x0 + 1},
                           {y0 * 16 + x0 + 16, y0 * 16 + x0 + 17}};

    // ---- z for slice 1 ----
    float fz = fminf(fmaxf((g + 1.0f) * 3.5f, 0.0f), 7.0f);
    int z0 = (int)fz;
    if (z0 > 7) z0 = 7;
    int z1 = min(z0 + 1, 7);
    float wz = fz - (float)z0;

    // ---- slice grid1 (channel-last, 8 x float4 per corner), fold into hid[8] ----
    float hid[8];
#pragma unroll
    for (int k = 0; k < 8; k++) hid[k] = 0.0f;

    {
        const float wza[2] = {1.0f - wz, wz};
        const int   za[2]  = {z0, z1};
#pragma unroll
        for (int zi = 0; zi < 2; zi++) {
            const int czb = (pb * 8 + za[zi]) * 256;
#pragma unroll
            for (int yi = 0; yi < 2; yi++) {
#pragma unroll
                for (int xi = 0; xi < 2; xi++) {
                    const float wc = wza[zi] * wya[yi] * wxa[xi];
                    const float4* p = (const float4*)(g1t + (czb + oxy[yi][xi]) * 32);
                    const float ws[4] = {wc * s0, wc * s1, wc * s2, wc};
#pragma unroll
                    for (int j = 0; j < 8; j++) {
                        const float4 v = __ldg(p + j);
                        const float m = ws[j >> 1];
                        const int k = (j & 1) * 4;
                        hid[k + 0] = fmaf(v.x, m, hid[k + 0]);
                        hid[k + 1] = fmaf(v.y, m, hid[k + 1]);
                        hid[k + 2] = fmaf(v.z, m, hid[k + 2]);
                        hid[k + 3] = fmaf(v.w, m, hid[k + 3]);
                    }
                }
            }
        }
    }
#pragma unroll
    for (int k = 0; k < 8; k++) hid[k] = fmaxf(hid[k], 0.0f);

    // ---- guide NN #2 ----
    float g2v = sb4s;
#pragma unroll
    for (int o = 0; o < 16; o++) {
        float t = sb3[o];
#pragma unroll
        for (int p = 0; p < 8; p++) t = fmaf(sw3[o * 8 + p], hid[p], t);
        t = fmaxf(t, 0.0f);
        g2v = fmaf(sw4[o], t, g2v);
    }
    g2v = tanhf(g2v);

    // ---- z for slice 2 ----
    fz = fminf(fmaxf((g2v + 1.0f) * 3.5f, 0.0f), 7.0f);
    z0 = (int)fz;
    if (z0 > 7) z0 = 7;
    z1 = min(z0 + 1, 7);
    wz = fz - (float)z0;

    // ---- slice grid2 (28 ch per corner = 7 x float4), fold into out[3] ----
    // channel c -> q = c%3 (out ch), p = c/3 (hidden ch; p==8 bias, p==9 pad)
    float r[3] = {0.0f, 0.0f, 0.0f};
    {
        float m2[10];
#pragma unroll
        for (int p = 0; p < 8; p++) m2[p] = hid[p];
        m2[8] = 1.0f;
        m2[9] = 0.0f;

        const float wza[2] = {1.0f - wz, wz};
        const int   za[2]  = {z0, z1};
#pragma unroll
        for (int zi = 0; zi < 2; zi++) {
            const int czb = (pb * 8 + za[zi]) * 256;
#pragma unroll
            for (int yi = 0; yi < 2; yi++) {
#pragma unroll
                for (int xi = 0; xi < 2; xi++) {
                    const float wc = wza[zi] * wya[yi] * wxa[xi];
                    const float4* p = (const float4*)(g2t + (czb + oxy[yi][xi]) * 28);
#pragma unroll
                    for (int j = 0; j < 7; j++) {
                        const float4 v = __ldg(p + j);
                        const int c0 = 4 * j;
                        r[(c0 + 0) % 3] = fmaf(v.x, wc * m2[(c0 + 0) / 3], r[(c0 + 0) % 3]);
                        r[(c0 + 1) % 3] = fmaf(v.y, wc * m2[(c0 + 1) / 3], r[(c0 + 1) % 3]);
                        r[(c0 + 2) % 3] = fmaf(v.z, wc * m2[(c0 + 2) / 3], r[(c0 + 2) % 3]);
                        r[(c0 + 3) % 3] = fmaf(v.w, wc * m2[(c0 + 3) / 3], r[(c0 + 3) % 3]);
                    }
                }
            }
        }
    }

    float* outp = out + (pb * 3) * HW + py * IMG_W + px;
    outp[0]      = r[0];
    outp[HW]     = r[1];
    outp[2 * HW] = r[2];
}

extern "C" void kernel_launch(void* const* d_in, const int* in_sizes, int n_in,
                              void* d_out, int out_size) {
    const float* src   = (const float*)d_in[0];
    const float* grid1 = (const float*)d_in[1];
    const float* grid2 = (const float*)d_in[2];
    const float* w1    = (const float*)d_in[3];
    const float* b1    = (const float*)d_in[4];
    const float* w2    = (const float*)d_in[5];
    const float* b2    = (const float*)d_in[6];
    const float* w3    = (const float*)d_in[7];
    const float* b3    = (const float*)d_in[8];
    const float* w4    = (const float*)d_in[9];
    const float* b4    = (const float*)d_in[10];
    float* out = (float*)d_out;

    // Pre-pass: channel-last transpose of both grids into device scratch.
    {
        const int total = 8 * 32 * 8 * 256;   // largest segment
        transpose_grids<<<(total + 255) / 256, 256>>>(grid1, grid2);
    }

    const int total = 8 * IMG_H * IMG_W;
    bgrid_fused_kernel<<<total / 256, 256>>>(src,
                                             w1, b1, w2, b2, w3, b3, w4, b4,
                                             out);
}